// round 2
// baseline (speedup 1.0000x reference)
#include <cuda_runtime.h>

#define MAX_NODES 100000
#define MAX_EDGES 1600000
#define D 64

// ---- static device scratch (no allocations allowed) ----
__device__ float g_deg[MAX_NODES];
__device__ float g_dis[MAX_NODES];
__device__ int   g_counts[MAX_NODES];
__device__ int   g_row_start[MAX_NODES];
__device__ int   g_cursor[MAX_NODES];
__device__ int   g_block_sums[1024];
__device__ int   g_src_sorted[MAX_EDGES];
__device__ float g_norm_sorted[MAX_EDGES];
__device__ float g_agg[MAX_NODES * D];
__device__ float g_h[MAX_NODES * D];
__device__ int   g_is32;   // 1 if edge_index is int32, 0 if int64

// ---------------------------------------------------------------------------
__global__ void k_init(int n) {
    int i = blockIdx.x * blockDim.x + threadIdx.x;
    if (i == 0) g_is32 = 0;
    if (i < n) { g_deg[i] = 1.0f; g_counts[i] = 0; }   // self-loop weight 1
}

// Probe dtype: as int64, an int32 buffer yields values >= 2^32 (two packed ids)
__global__ void k_detect(const long long* __restrict__ ei, int E, int n) {
    int i = threadIdx.x;
    if (i < E) {
        long long v = ei[i];
        if (v < 0 || v >= (long long)n) atomicOr(&g_is32, 1);
    }
}

__device__ __forceinline__ int load_idx(const void* ei, int E, int pos, int is32, int n) {
    int v;
    if (is32) v = ((const int*)ei)[pos];
    else      v = (int)((const long long*)ei)[pos];
    // clamp for safety: wrong detection -> numeric mismatch, not a trap
    return v < 0 ? 0 : (v >= n ? n - 1 : v);
}

__global__ void k_edge_deg(const void* __restrict__ ei,
                           const float* __restrict__ w, int E, int n) {
    int e = blockIdx.x * blockDim.x + threadIdx.x;
    if (e < E) {
        int is32 = g_is32;
        int dst = load_idx(ei, E, E + e, is32, n);
        atomicAdd(&g_deg[dst], w[e]);
        atomicAdd(&g_counts[dst], 1);
    }
}

__global__ void k_dis(int n) {
    int i = blockIdx.x * blockDim.x + threadIdx.x;
    if (i < n) g_dis[i] = rsqrtf(g_deg[i]);   // deg >= 1 always (self loop)
}

// --- exclusive scan of g_counts -> g_row_start (3-kernel classic) ---
__global__ void k_scan_local(int n) {
    __shared__ int sh[1024];
    int tid = threadIdx.x;
    int gid = blockIdx.x * 1024 + tid;
    int v = (gid < n) ? g_counts[gid] : 0;
    sh[tid] = v;
    __syncthreads();
    for (int off = 1; off < 1024; off <<= 1) {
        int t = (tid >= off) ? sh[tid - off] : 0;
        __syncthreads();
        sh[tid] += t;
        __syncthreads();
    }
    if (gid < n) g_row_start[gid] = sh[tid] - v;       // exclusive
    if (tid == 1023) g_block_sums[blockIdx.x] = sh[1023];
}

__global__ void k_scan_top(int nb) {
    __shared__ int sh[1024];
    int tid = threadIdx.x;
    int v = (tid < nb) ? g_block_sums[tid] : 0;
    sh[tid] = v;
    __syncthreads();
    for (int off = 1; off < 1024; off <<= 1) {
        int t = (tid >= off) ? sh[tid - off] : 0;
        __syncthreads();
        sh[tid] += t;
        __syncthreads();
    }
    if (tid < nb) g_block_sums[tid] = sh[tid] - v;     // exclusive block offsets
}

__global__ void k_scan_add(int n) {
    int gid = blockIdx.x * 1024 + threadIdx.x;
    if (gid < n) {
        int s = g_row_start[gid] + g_block_sums[blockIdx.x];
        g_row_start[gid] = s;
        g_cursor[gid]    = s;
    }
}

// --- CSR-by-dst scatter: also precompute per-edge normalization ---
__global__ void k_build(const void* __restrict__ ei,
                        const float* __restrict__ w, int E, int n) {
    int e = blockIdx.x * blockDim.x + threadIdx.x;
    if (e < E) {
        int is32 = g_is32;
        int s = load_idx(ei, E, e, is32, n);
        int d = load_idx(ei, E, E + e, is32, n);
        int pos = atomicAdd(&g_cursor[d], 1);
        g_src_sorted[pos]  = s;
        g_norm_sorted[pos] = g_dis[s] * w[e] * g_dis[d];
    }
}

// --- aggregation: one warp per node, lane = float2 column pair ---
// After k_build, g_cursor[i] == row_start[i] + count[i] == row end.
__global__ void k_gather(const float* __restrict__ hx, int use_internal, int n) {
    const float* h = use_internal ? g_h : hx;
    int node = (blockIdx.x * blockDim.x + threadIdx.x) >> 5;
    int lane = threadIdx.x & 31;
    if (node >= n) return;

    const float2* hv = (const float2*)h;
    float dis = g_dis[node];
    float dd = dis * dis;
    float2 sv = hv[node * 32 + lane];
    float2 acc = make_float2(sv.x * dd, sv.y * dd);   // self loop term

    int e   = g_row_start[node];
    int end = g_cursor[node];
    while (e + 2 <= end) {
        int   s0 = g_src_sorted[e];
        int   s1 = g_src_sorted[e + 1];
        float n0 = g_norm_sorted[e];
        float n1 = g_norm_sorted[e + 1];
        float2 v0 = hv[s0 * 32 + lane];
        float2 v1 = hv[s1 * 32 + lane];
        acc.x += v0.x * n0; acc.y += v0.y * n0;
        acc.x += v1.x * n1; acc.y += v1.y * n1;
        e += 2;
    }
    if (e < end) {
        int   s0 = g_src_sorted[e];
        float n0 = g_norm_sorted[e];
        float2 v0 = hv[s0 * 32 + lane];
        acc.x += v0.x * n0; acc.y += v0.y * n0;
    }
    ((float2*)g_agg)[node * 32 + lane] = acc;
}

// --- fused GEMM (agg @ W) + bias + optional relu ---
// 256 threads: 32 rows/block, each thread -> 8 output cols via float4 LDS.
__global__ void k_gemm(const float* __restrict__ W, const float* __restrict__ b,
                       float* __restrict__ outx, int write_internal, int relu, int n) {
    float* out = write_internal ? g_h : outx;
    __shared__ __align__(16) float Wsh[64][64];
    __shared__ float Ash[32][65];
    int tid = threadIdx.x;
    int row0 = blockIdx.x * 32;

    for (int i = tid; i < 64 * 64; i += 256)
        Wsh[i >> 6][i & 63] = W[i];
    for (int i = tid; i < 32 * 64; i += 256) {
        int r = i >> 6, c = i & 63;
        int row = row0 + r;
        Ash[r][c] = (row < n) ? g_agg[row * 64 + c] : 0.0f;
    }
    __syncthreads();

    int r  = tid >> 3;
    int cx = tid & 7;
    int c0 = cx * 8;
    float4 a0 = make_float4(0.f, 0.f, 0.f, 0.f);
    float4 a1 = make_float4(0.f, 0.f, 0.f, 0.f);
#pragma unroll
    for (int k = 0; k < 64; k++) {
        float hk = Ash[r][k];
        float4 w0 = *(const float4*)&Wsh[k][c0];
        float4 w1 = *(const float4*)&Wsh[k][c0 + 4];
        a0.x += hk * w0.x; a0.y += hk * w0.y; a0.z += hk * w0.z; a0.w += hk * w0.w;
        a1.x += hk * w1.x; a1.y += hk * w1.y; a1.z += hk * w1.z; a1.w += hk * w1.w;
    }
    int row = row0 + r;
    if (row < n) {
        float4 b0 = *(const float4*)&b[c0];
        float4 b1 = *(const float4*)&b[c0 + 4];
        a0.x += b0.x; a0.y += b0.y; a0.z += b0.z; a0.w += b0.w;
        a1.x += b1.x; a1.y += b1.y; a1.z += b1.z; a1.w += b1.w;
        if (relu) {
            a0.x = fmaxf(a0.x, 0.f); a0.y = fmaxf(a0.y, 0.f);
            a0.z = fmaxf(a0.z, 0.f); a0.w = fmaxf(a0.w, 0.f);
            a1.x = fmaxf(a1.x, 0.f); a1.y = fmaxf(a1.y, 0.f);
            a1.z = fmaxf(a1.z, 0.f); a1.w = fmaxf(a1.w, 0.f);
        }
        *(float4*)&out[row * 64 + c0]     = a0;
        *(float4*)&out[row * 64 + c0 + 4] = a1;
    }
}

// ---------------------------------------------------------------------------
extern "C" void kernel_launch(void* const* d_in, const int* in_sizes, int n_in,
                              void* d_out, int out_size) {
    const float* x  = (const float*)d_in[0];
    const void*  ei = d_in[1];
    const float* w  = (const float*)d_in[2];
    const float* W1 = (const float*)d_in[3];
    const float* b1 = (const float*)d_in[4];
    const float* W2 = (const float*)d_in[5];
    const float* b2 = (const float*)d_in[6];
    const float* W3 = (const float*)d_in[7];
    const float* b3 = (const float*)d_in[8];
    float* out = (float*)d_out;

    int n = in_sizes[0] / D;      // 100000
    int E = in_sizes[1] / 2;      // 1600000

    const int tb = 256;
    int nblk_n = (n + tb - 1) / tb;
    int nblk_e = (E + tb - 1) / tb;
    int nb = (n + 1023) / 1024;

    k_init<<<nblk_n, tb>>>(n);
    k_detect<<<1, 256>>>((const long long*)ei, E, n);
    k_edge_deg<<<nblk_e, tb>>>(ei, w, E, n);
    k_dis<<<nblk_n, tb>>>(n);
    k_scan_local<<<nb, 1024>>>(n);
    k_scan_top<<<1, 1024>>>(nb);
    k_scan_add<<<nb, 1024>>>(n);
    k_build<<<nblk_e, tb>>>(ei, w, E, n);

    int gblocks = (n * 32 + tb - 1) / tb;   // one warp per node
    int mblocks = (n + 31) / 32;

    k_gather<<<gblocks, tb>>>(x, 0, n);
    k_gemm<<<mblocks, 256>>>(W1, b1, nullptr, 1, 1, n);
    k_gather<<<gblocks, tb>>>(nullptr, 1, n);
    k_gemm<<<mblocks, 256>>>(W2, b2, nullptr, 1, 1, n);
    k_gather<<<gblocks, tb>>>(nullptr, 1, n);
    k_gemm<<<mblocks, 256>>>(W3, b3, out, 0, 0, n);
}

// round 3
// speedup vs baseline: 1.7081x; 1.7081x over previous
#include <cuda_runtime.h>
#include <cuda_fp16.h>

#define MAX_NODES 100000
#define MAX_EDGES 1600000
#define D 64

// ---- static device scratch (no allocations allowed) ----
__device__ float   g_deg[MAX_NODES];
__device__ float   g_dis[MAX_NODES];
__device__ int     g_counts[MAX_NODES];
__device__ int     g_row_start[MAX_NODES];
__device__ int     g_cursor[MAX_NODES];
__device__ int     g_block_sums[1024];
__device__ int2    g_edge[MAX_EDGES];          // {src, norm as float bits}
__device__ float   g_agg[MAX_NODES * D];       // aggregation result (fp32)
__device__ __half2 g_h16[MAX_NODES * 32];      // intermediate features (fp16)
__device__ int     g_is32;

// ---------------------------------------------------------------------------
__global__ void k_init(int n) {
    int i = blockIdx.x * blockDim.x + threadIdx.x;
    if (i == 0) g_is32 = 0;
    if (i < n) { g_deg[i] = 1.0f; g_counts[i] = 0; }   // self-loop weight 1
}

// Probe dtype: interpreting an int32 buffer as int64 packs two ids per word ->
// values >= 2^32 (unless the high id is 0) -> flag fires with prob ~1-(1e-5)^256.
__global__ void k_detect(const long long* __restrict__ ei, int E, int n) {
    int i = threadIdx.x;
    if (i < E) {
        long long v = ei[i];
        if (v < 0 || v >= (long long)n) atomicOr(&g_is32, 1);
    }
}

__device__ __forceinline__ int load_idx(const void* ei, int pos, int is32, int n) {
    int v;
    if (is32) v = ((const int*)ei)[pos];
    else      v = (int)((const long long*)ei)[pos];
    return v < 0 ? 0 : (v >= n ? n - 1 : v);
}

__global__ void k_edge_deg(const void* __restrict__ ei,
                           const float* __restrict__ w, int E, int n) {
    int e = blockIdx.x * blockDim.x + threadIdx.x;
    if (e < E) {
        int is32 = g_is32;
        int dst = load_idx(ei, E + e, is32, n);
        atomicAdd(&g_deg[dst], w[e]);
        atomicAdd(&g_counts[dst], 1);
    }
}

__global__ void k_dis(int n) {
    int i = blockIdx.x * blockDim.x + threadIdx.x;
    if (i < n) g_dis[i] = rsqrtf(g_deg[i]);
}

// --- exclusive scan of g_counts -> g_row_start ---
__global__ void k_scan_local(int n) {
    __shared__ int sh[1024];
    int tid = threadIdx.x;
    int gid = blockIdx.x * 1024 + tid;
    int v = (gid < n) ? g_counts[gid] : 0;
    sh[tid] = v;
    __syncthreads();
    for (int off = 1; off < 1024; off <<= 1) {
        int t = (tid >= off) ? sh[tid - off] : 0;
        __syncthreads();
        sh[tid] += t;
        __syncthreads();
    }
    if (gid < n) g_row_start[gid] = sh[tid] - v;
    if (tid == 1023) g_block_sums[blockIdx.x] = sh[1023];
}

__global__ void k_scan_top(int nb) {
    __shared__ int sh[1024];
    int tid = threadIdx.x;
    int v = (tid < nb) ? g_block_sums[tid] : 0;
    sh[tid] = v;
    __syncthreads();
    for (int off = 1; off < 1024; off <<= 1) {
        int t = (tid >= off) ? sh[tid - off] : 0;
        __syncthreads();
        sh[tid] += t;
        __syncthreads();
    }
    if (tid < nb) g_block_sums[tid] = sh[tid] - v;
}

__global__ void k_scan_add(int n) {
    int gid = blockIdx.x * 1024 + threadIdx.x;
    if (gid < n) {
        int s = g_row_start[gid] + g_block_sums[blockIdx.x];
        g_row_start[gid] = s;
        g_cursor[gid]    = s;
    }
}

// --- CSR-by-dst scatter with packed (src, norm) 8B record ---
__global__ void k_build(const void* __restrict__ ei,
                        const float* __restrict__ w, int E, int n) {
    int e = blockIdx.x * blockDim.x + threadIdx.x;
    if (e < E) {
        int is32 = g_is32;
        int s = load_idx(ei, e, is32, n);
        int d = load_idx(ei, E + e, is32, n);
        int pos = atomicAdd(&g_cursor[d], 1);
        float nm = g_dis[s] * w[e] * g_dis[d];
        g_edge[pos] = make_int2(s, __float_as_int(nm));
    }
}

// --- aggregation: one warp per node. IN_HALF: row=128B, else row=256B ---
template<bool IN_HALF>
__global__ void k_gather(const float* __restrict__ xin, int n) {
    int node = (blockIdx.x * blockDim.x + threadIdx.x) >> 5;
    int lane = threadIdx.x & 31;
    if (node >= n) return;

    float dd = g_dis[node];
    dd *= dd;
    float2 acc;
    int e   = g_row_start[node];
    int end = g_cursor[node];

    if (IN_HALF) {
        const __half2* hv = g_h16;
        float2 sv = __half22float2(hv[node * 32 + lane]);
        acc.x = sv.x * dd; acc.y = sv.y * dd;
        while (e + 2 <= end) {
            int2 e0 = g_edge[e];
            int2 e1 = g_edge[e + 1];
            float2 v0 = __half22float2(hv[e0.x * 32 + lane]);
            float2 v1 = __half22float2(hv[e1.x * 32 + lane]);
            float n0 = __int_as_float(e0.y);
            float n1 = __int_as_float(e1.y);
            acc.x += v0.x * n0; acc.y += v0.y * n0;
            acc.x += v1.x * n1; acc.y += v1.y * n1;
            e += 2;
        }
        if (e < end) {
            int2 e0 = g_edge[e];
            float2 v0 = __half22float2(hv[e0.x * 32 + lane]);
            float n0 = __int_as_float(e0.y);
            acc.x += v0.x * n0; acc.y += v0.y * n0;
        }
    } else {
        const float2* hv = (const float2*)xin;
        float2 sv = hv[node * 32 + lane];
        acc.x = sv.x * dd; acc.y = sv.y * dd;
        while (e + 2 <= end) {
            int2 e0 = g_edge[e];
            int2 e1 = g_edge[e + 1];
            float2 v0 = hv[e0.x * 32 + lane];
            float2 v1 = hv[e1.x * 32 + lane];
            float n0 = __int_as_float(e0.y);
            float n1 = __int_as_float(e1.y);
            acc.x += v0.x * n0; acc.y += v0.y * n0;
            acc.x += v1.x * n1; acc.y += v1.y * n1;
            e += 2;
        }
        if (e < end) {
            int2 e0 = g_edge[e];
            float2 v0 = hv[e0.x * 32 + lane];
            float n0 = __int_as_float(e0.y);
            acc.x += v0.x * n0; acc.y += v0.y * n0;
        }
    }
    ((float2*)g_agg)[node * 32 + lane] = acc;
}

// --- GEMM (agg @ W) + bias (+relu): 128 rows/block, 256 thr, 4x8 reg tile ---
__global__ void __launch_bounds__(256) k_gemm(
    const float* __restrict__ W, const float* __restrict__ b,
    float* __restrict__ outx, int out_half, int relu, int n)
{
    __shared__ float Wsh[64][64];    // [k][c]  16KB
    __shared__ float At[64][128];    // [k][r]  32KB (transposed A tile)
    int tid  = threadIdx.x;
    int row0 = blockIdx.x * 128;

    for (int i = tid; i < 4096; i += 256)
        Wsh[i >> 6][i & 63] = W[i];

    // load 128x64 A tile, transposed into At
    {
        int r = tid >> 1;                 // 0..127
        int h = (tid & 1) * 32;           // column half
        int grow = row0 + r;
        const float4* src = (const float4*)&g_agg[grow * 64 + h];
#pragma unroll
        for (int j = 0; j < 8; j++) {
            float4 v = (grow < n) ? src[j] : make_float4(0.f, 0.f, 0.f, 0.f);
            int c = h + j * 4;
            At[c + 0][r] = v.x; At[c + 1][r] = v.y;
            At[c + 2][r] = v.z; At[c + 3][r] = v.w;
        }
    }
    __syncthreads();

    int r0 = (tid >> 3) << 2;   // 0,4,...,124
    int c0 = (tid & 7) << 3;    // 0,8,...,56

    float acc[4][8];
#pragma unroll
    for (int i = 0; i < 4; i++)
#pragma unroll
        for (int j = 0; j < 8; j++) acc[i][j] = 0.f;

#pragma unroll 8
    for (int k = 0; k < 64; k++) {
        float4 a  = *(const float4*)&At[k][r0];
        float4 w0 = *(const float4*)&Wsh[k][c0];
        float4 w1 = *(const float4*)&Wsh[k][c0 + 4];
        float av[4] = {a.x, a.y, a.z, a.w};
#pragma unroll
        for (int i = 0; i < 4; i++) {
            acc[i][0] += av[i] * w0.x; acc[i][1] += av[i] * w0.y;
            acc[i][2] += av[i] * w0.z; acc[i][3] += av[i] * w0.w;
            acc[i][4] += av[i] * w1.x; acc[i][5] += av[i] * w1.y;
            acc[i][6] += av[i] * w1.z; acc[i][7] += av[i] * w1.w;
        }
    }

    float4 b0 = *(const float4*)&b[c0];
    float4 b1 = *(const float4*)&b[c0 + 4];
    float bb[8] = {b0.x, b0.y, b0.z, b0.w, b1.x, b1.y, b1.z, b1.w};

#pragma unroll
    for (int i = 0; i < 4; i++) {
        int grow = row0 + r0 + i;
        if (grow >= n) continue;
        float v[8];
#pragma unroll
        for (int j = 0; j < 8; j++) {
            float t = acc[i][j] + bb[j];
            v[j] = relu ? fmaxf(t, 0.f) : t;
        }
        if (out_half) {
            __half2* dst = &g_h16[grow * 32 + (c0 >> 1)];
            dst[0] = __floats2half2_rn(v[0], v[1]);
            dst[1] = __floats2half2_rn(v[2], v[3]);
            dst[2] = __floats2half2_rn(v[4], v[5]);
            dst[3] = __floats2half2_rn(v[6], v[7]);
        } else {
            float4* dst = (float4*)&outx[grow * 64 + c0];
            dst[0] = make_float4(v[0], v[1], v[2], v[3]);
            dst[1] = make_float4(v[4], v[5], v[6], v[7]);
        }
    }
}

// ---------------------------------------------------------------------------
extern "C" void kernel_launch(void* const* d_in, const int* in_sizes, int n_in,
                              void* d_out, int out_size) {
    const float* x  = (const float*)d_in[0];
    const void*  ei = d_in[1];
    const float* w  = (const float*)d_in[2];
    const float* W1 = (const float*)d_in[3];
    const float* b1 = (const float*)d_in[4];
    const float* W2 = (const float*)d_in[5];
    const float* b2 = (const float*)d_in[6];
    const float* W3 = (const float*)d_in[7];
    const float* b3 = (const float*)d_in[8];
    float* out = (float*)d_out;

    int n = in_sizes[0] / D;      // 100000
    int E = in_sizes[1] / 2;      // 1600000

    const int tb = 256;
    int nblk_n = (n + tb - 1) / tb;
    int nblk_e = (E + tb - 1) / tb;
    int nb = (n + 1023) / 1024;

    k_init<<<nblk_n, tb>>>(n);
    k_detect<<<1, 256>>>((const long long*)ei, E, n);
    k_edge_deg<<<nblk_e, tb>>>(ei, w, E, n);
    k_dis<<<nblk_n, tb>>>(n);
    k_scan_local<<<nb, 1024>>>(n);
    k_scan_top<<<1, 1024>>>(nb);
    k_scan_add<<<nb, 1024>>>(n);
    k_build<<<nblk_e, tb>>>(ei, w, E, n);

    int gblocks = (n * 32 + tb - 1) / tb;   // one warp per node
    int mblocks = (n + 127) / 128;

    k_gather<false><<<gblocks, tb>>>(x, n);
    k_gemm<<<mblocks, 256>>>(W1, b1, nullptr, 1, 1, n);
    k_gather<true><<<gblocks, tb>>>(nullptr, n);
    k_gemm<<<mblocks, 256>>>(W2, b2, nullptr, 1, 1, n);
    k_gather<true><<<gblocks, tb>>>(nullptr, n);
    k_gemm<<<mblocks, 256>>>(W3, b3, out, 0, 0, n);
}